// round 14
// baseline (speedup 1.0000x reference)
#include <cuda_runtime.h>
#include <cuda_fp16.h>
#include <math.h>
#include <stdint.h>

#define BB 2
#define TT 2048
#define CC 1024
#define HH 16
#define DHD 64
#define NTOK (BB*TT)   // 4096

// Scratch (allocation-free: __device__ globals)
__device__ __half g_xh[NTOK*CC];        // x as f16
__device__ __half g_q[BB*HH*TT*DHD];    // f16, [bh][t][d]
__device__ __half g_k[BB*HH*TT*DHD];    // f16, [bh][t][d]
__device__ __half g_vt[BB*HH*DHD*TT];   // f16, TRANSPOSED [bh][d][t]
__device__ __half g_ao[NTOK*CC];        // attention out f16, token-major
__device__ __half g_wqkvT[3*CC*CC];     // W_qkv^T f16, [3072][1024]
__device__ __half g_wprojT[CC*CC];      // W_proj^T f16, [1024][1024]

// ---------------------------------------------------------------------------
__device__ __forceinline__ float ex2(float x) {
    float r; asm("ex2.approx.f32 %0, %1;" : "=f"(r) : "f"(x)); return r;
}
__device__ __forceinline__ uint32_t smem_u32(const void* p) {
    return (uint32_t)__cvta_generic_to_shared(p);
}
__device__ __forceinline__ void ldsm4(uint32_t& r0, uint32_t& r1, uint32_t& r2,
                                      uint32_t& r3, uint32_t a) {
    asm volatile("ldmatrix.sync.aligned.m8n8.x4.shared.b16 {%0,%1,%2,%3},[%4];"
                 : "=r"(r0), "=r"(r1), "=r"(r2), "=r"(r3) : "r"(a));
}
// f16 MMA: D(f32) += A(f16 m16k16) * B(f16 k16n8)
__device__ __forceinline__ void mma16(float4& d, const uint32_t* a,
                                      uint32_t b0, uint32_t b1) {
    asm volatile("mma.sync.aligned.m16n8k16.row.col.f32.f16.f16.f32 "
                 "{%0,%1,%2,%3},{%4,%5,%6,%7},{%8,%9},{%0,%1,%2,%3};"
                 : "+f"(d.x), "+f"(d.y), "+f"(d.z), "+f"(d.w)
                 : "r"(a[0]), "r"(a[1]), "r"(a[2]), "r"(a[3]), "r"(b0), "r"(b1));
}
__device__ __forceinline__ void cp16(uint32_t s, const void* g) {
    asm volatile("cp.async.cg.shared.global [%0], [%1], 16;" :: "r"(s), "l"(g));
}
__device__ __forceinline__ void cp_commit() {
    asm volatile("cp.async.commit_group;");
}
template<int N>
__device__ __forceinline__ void cp_wait() {
    asm volatile("cp.async.wait_group %0;" :: "n"(N));
}

// ---------------------------------------------------------------------------
__global__ void cvt_f32_f16(const float* __restrict__ in, __half* __restrict__ out,
                            int n4)
{
    int i = blockIdx.x * blockDim.x + threadIdx.x;
    if (i < n4) {
        float4 v = ((const float4*)in)[i];
        __half2 h0 = __floats2half2_rn(v.x, v.y);
        __half2 h1 = __floats2half2_rn(v.z, v.w);
        ((uint2*)out)[i] = make_uint2(*(uint32_t*)&h0, *(uint32_t*)&h1);
    }
}

// Transpose + f16-convert: Wt[n*K + k] = f16(W[k*N + n])
__global__ void transpose_cvt_h(const float* __restrict__ W, __half* __restrict__ Wt,
                                int K, int N)
{
    __shared__ float tile[32][33];
    const int n0 = blockIdx.x * 32, k0 = blockIdx.y * 32;
    const int tx = threadIdx.x, ty = threadIdx.y;
    #pragma unroll
    for (int i = ty; i < 32; i += 8)
        tile[i][tx] = W[(size_t)(k0 + i) * N + n0 + tx];
    __syncthreads();
    #pragma unroll
    for (int i = ty; i < 32; i += 8)
        Wt[(size_t)(n0 + i) * K + k0 + tx] = __float2half_rn(tile[tx][i]);
}

// ---------------------------------------------------------------------------
// f16 tensor-core GEMM, 256x128 CTA tile, 512 threads (16 warps of 64x32),
// K-tile = 64 (four k16 sub-steps), 3-stage cp.async ring.
// Rows padded to 144 B (conflict-free LDSM: 144/4=36 = 4 mod 32).
// MODE 0: scatter into g_q/g_k (f16, [bh][t][d]) and g_vt (f16, [bh][d][t])
// MODE 1: fp32 epilogue into Out
// ---------------------------------------------------------------------------
#define ASTG 36864     // A stage: 256 rows x 144 B
#define BSTG 18432     // B stage: 128 rows x 144 B

template<int MODE>
__global__ __launch_bounds__(512, 1)
void mma_gemm(const __half* __restrict__ A, const __half* __restrict__ Bt,
              const float* __restrict__ bias, float* __restrict__ Out,
              int M, int N, int K)
{
    extern __shared__ __align__(16) char dsm[];
    const uint32_t sA = smem_u32(dsm);            // 3 stages A
    const uint32_t sB = sA + 3 * ASTG;            // 3 stages B

    const int row0 = blockIdx.y * 256, col0 = blockIdx.x * 128;
    const int tid = threadIdx.x, lane = tid & 31, wid = tid >> 5;
    const int wm = (wid >> 2) * 64, wn = (wid & 3) * 32;
    const int g = lane >> 2, tg = lane & 3;

    float4 c[4][4];
    #pragma unroll
    for (int i = 0; i < 4; i++)
        #pragma unroll
        for (int j = 0; j < 4; j++) c[i][j] = make_float4(0.f, 0.f, 0.f, 0.f);

    const uint32_t aBase = sA + (wm + (lane & 15)) * 144 + (lane >> 4) * 16;
    const uint32_t bBase = sB + (wn + ((lane >> 4) << 3) + (lane & 7)) * 144
                              + ((lane >> 3) & 1) * 16;

    const int NKT = K / 64;   // 16

    auto issueAB = [&](int kt, int buf) {
        #pragma unroll
        for (int i = 0; i < 4; i++) {
            int idx = tid + i * 512;
            int r = idx >> 3, c8 = idx & 7;
            cp16(sA + buf * ASTG + r * 144 + c8 * 16,
                 A + (size_t)(row0 + r) * K + kt * 64 + c8 * 8);
        }
        #pragma unroll
        for (int i = 0; i < 2; i++) {
            int idx = tid + i * 512;
            int r = idx >> 3, c8 = idx & 7;
            cp16(sB + buf * BSTG + r * 144 + c8 * 16,
                 Bt + (size_t)(col0 + r) * K + kt * 64 + c8 * 8);
        }
        cp_commit();
    };

    issueAB(0, 0); issueAB(1, 1);

    for (int kt = 0; kt < NKT; kt++) {
        if (kt + 1 < NKT) cp_wait<1>();
        else              cp_wait<0>();
        __syncthreads();
        if (kt + 2 < NKT) issueAB(kt + 2, (kt + 2) % 3);

        const int buf = kt % 3;
        const uint32_t aB = aBase + buf * ASTG;
        const uint32_t bB = bBase + buf * BSTG;
        #pragma unroll
        for (int s = 0; s < 4; s++) {
            uint32_t af[4][4], bf[4][2];
            #pragma unroll
            for (int fm = 0; fm < 4; fm++)
                ldsm4(af[fm][0], af[fm][1], af[fm][2], af[fm][3],
                      aB + fm * (16 * 144) + s * 32);
            #pragma unroll
            for (int cb = 0; cb < 2; cb++)
                ldsm4(bf[2*cb][0], bf[2*cb][1], bf[2*cb+1][0], bf[2*cb+1][1],
                      bB + cb * (16 * 144) + s * 32);
            #pragma unroll
            for (int fm = 0; fm < 4; fm++)
                #pragma unroll
                for (int fn = 0; fn < 4; fn++)
                    mma16(c[fm][fn], af[fm], bf[fn][0], bf[fn][1]);
        }
    }

    #pragma unroll
    for (int fm = 0; fm < 4; fm++) {
        #pragma unroll
        for (int fn = 0; fn < 4; fn++) {
            const int m0 = row0 + wm + fm * 16 + g;
            const int m1 = m0 + 8;
            const int n  = col0 + wn + fn * 8 + 2 * tg;
            const float b0v = bias[n], b1v = bias[n + 1];
            float2 lo = make_float2(c[fm][fn].x + b0v, c[fm][fn].y + b1v);
            float2 hi = make_float2(c[fm][fn].z + b0v, c[fm][fn].w + b1v);
            if (MODE == 0) {
                const int which = n >> 10, cc = n & 1023, h = cc >> 6, d = cc & 63;
                const int b = m0 >> 11, t = m0 & 2047;   // same b for m0, m1
                if (which < 2) {
                    __half* dst = (which == 0) ? g_q : g_k;
                    *(__half2*)&dst[((size_t)((b * HH + h) * TT + t)) * DHD + d] =
                        __floats2half2_rn(lo.x, lo.y);
                    *(__half2*)&dst[((size_t)((b * HH + h) * TT + t + 8)) * DHD + d] =
                        __floats2half2_rn(hi.x, hi.y);
                } else {
                    __half* dst = g_vt + (size_t)(b * HH + h) * DHD * TT;
                    dst[(size_t)d * TT + t]           = __float2half_rn(lo.x);
                    dst[(size_t)(d + 1) * TT + t]     = __float2half_rn(lo.y);
                    dst[(size_t)d * TT + t + 8]       = __float2half_rn(hi.x);
                    dst[(size_t)(d + 1) * TT + t + 8] = __float2half_rn(hi.y);
                }
            } else {
                *(float2*)&Out[(size_t)m0 * N + n] = lo;
                *(float2*)&Out[(size_t)m1 * N + n] = hi;
            }
        }
    }
}

// ---------------------------------------------------------------------------
// f16 tensor-core causal flash attention, 128-row q tiles x 128-key smem tiles
// processed as two 64-key halves (s[8] regs -> ~120 regs -> 2 CTAs/SM).
// 256 threads (8 warps x m16), 2-stage cp.async KV ring.
// K rows 144 B, V^T rows 272 B (both conflict-free for LDSM).
// ---------------------------------------------------------------------------
#define QB2 18432     // Q tile: 128 x 144 B
#define KTB 18432     // K tile: 128 rows x 144 B
#define VTB 17408     // V^T tile: 64 rows x 272 B
#define SCL2E 0.1803368801111204f   // (1/8) * log2(e)

__global__ __launch_bounds__(256, 2)
void attn_kernel()
{
    extern __shared__ __align__(16) char smc[];
    __half* Ps = (__half*)smc;                  // aliases Q (rows 72 halves)
    const uint32_t sQ = smem_u32(smc);
    const uint32_t sK = sQ + QB2;               // 2 x KTB
    const uint32_t sV = sK + 2 * KTB;           // 2 x VTB

    const int bh = blockIdx.y;
    const int qt = (int)gridDim.x - 1 - (int)blockIdx.x;  // big tiles first
    const int q0 = qt * 128;
    const int tid = threadIdx.x, lane = tid & 31, wid = tid >> 5;
    const int wm = wid * 16;
    const int g = lane >> 2, tg = lane & 3;

    const __half* Qg = g_q  + (size_t)bh * TT * DHD;
    const __half* Kg = g_k  + (size_t)bh * TT * DHD;
    const __half* Vg = g_vt + (size_t)bh * DHD * TT;

    auto issueKV = [&](int kt, int buf) {
        const int k0 = kt * 128;
        #pragma unroll
        for (int i = 0; i < 4; i++) {
            int idx = tid + i * 256;
            int r = idx >> 3, c8 = idx & 7;
            cp16(sK + buf * KTB + r * 144 + c8 * 16,
                 Kg + (size_t)(k0 + r) * DHD + c8 * 8);
        }
        #pragma unroll
        for (int i = 0; i < 4; i++) {
            int idx = tid + i * 256;
            int r = idx >> 4, c16 = idx & 15;
            cp16(sV + buf * VTB + r * 272 + c16 * 16,
                 Vg + (size_t)r * TT + k0 + c16 * 8);
        }
        cp_commit();
    };

    const int NT = qt + 1;

    // prologue: Q + KV0 (group 0), KV1 (group 1; keys [128,256) always exist)
    #pragma unroll
    for (int i = 0; i < 4; i++) {
        int idx = tid + i * 256;
        int r = idx >> 3, c8 = idx & 7;
        cp16(sQ + r * 144 + c8 * 16, Qg + (size_t)(q0 + r) * DHD + c8 * 8);
    }
    issueKV(0, 0);   // commits Q too (same group)
    issueKV(1, 1);

    // ldmatrix bases
    const uint32_t aQ = sQ + (wm + (lane & 15)) * 144 + (lane >> 4) * 16;
    const uint32_t kOffK = (((lane >> 4) << 3) + (lane & 7)) * 144
                         + ((lane >> 3) & 1) * 16;
    const uint32_t kOffV = (((lane >> 4) << 3) + (lane & 7)) * 272
                         + ((lane >> 3) & 1) * 16;
    const uint32_t aP = aQ;   // Ps aliases Qs

    uint32_t qf[4][4];
    float4 o[8];
    #pragma unroll
    for (int fn = 0; fn < 8; fn++) o[fn] = make_float4(0.f, 0.f, 0.f, 0.f);
    float m0 = -INFINITY, m1 = -INFINITY, l0 = 0.f, l1 = 0.f;
    const int r0g = q0 + wm + g, r1g = r0g + 8;

    for (int kt = 0; kt < NT; kt++) {
        const int k0 = kt * 128;
        if (kt + 1 < NT) cp_wait<1>();
        else             cp_wait<0>();
        __syncthreads();

        if (kt == 0) {
            #pragma unroll
            for (int kc = 0; kc < 4; kc++)
                ldsm4(qf[kc][0], qf[kc][1], qf[kc][2], qf[kc][3], aQ + kc * 32);
        }

        const int buf = kt & 1;
        const uint32_t bK = sK + buf * KTB + kOffK;
        const uint32_t bV = sV + buf * VTB + kOffV;
        const bool last = (kt == NT - 1);

        // process the 128-key tile as two 64-key halves (keeps regs low)
        #pragma unroll
        for (int h = 0; h < 2; h++) {
            const int kh0 = k0 + h * 64;
            // diagonal tile: skip a half that is entirely above this warp's rows
            if (last && kh0 > q0 + wm + 15) continue;

            // S_half = Q K^T  (m16 x n64), raw scores
            float4 s[8];
            #pragma unroll
            for (int fn = 0; fn < 8; fn++) s[fn] = make_float4(0.f, 0.f, 0.f, 0.f);
            #pragma unroll
            for (int kc = 0; kc < 4; kc++) {
                #pragma unroll
                for (int cb = 0; cb < 4; cb++) {
                    uint32_t b0, b1, b2, b3;
                    ldsm4(b0, b1, b2, b3,
                          bK + (4 * h + cb) * (16 * 144) + kc * 32);
                    mma16(s[2*cb],   qf[kc], b0, b1);
                    mma16(s[2*cb+1], qf[kc], b2, b3);
                }
            }

            // causal mask (diagonal tile only)
            if (last && kh0 + 63 > q0 + wm) {
                #pragma unroll
                for (int fn = 0; fn < 8; fn++) {
                    int c0 = kh0 + fn * 8 + 2 * tg, c1 = c0 + 1;
                    if (c0 > r0g) s[fn].x = -INFINITY;
                    if (c1 > r0g) s[fn].y = -INFINITY;
                    if (c0 > r1g) s[fn].z = -INFINITY;
                    if (c1 > r1g) s[fn].w = -INFINITY;
                }
            }

            // online softmax in base-2 domain (rows g, g+8)
            float rmax0 = -INFINITY, rmax1 = -INFINITY;
            #pragma unroll
            for (int fn = 0; fn < 8; fn++) {
                rmax0 = fmaxf(rmax0, fmaxf(s[fn].x, s[fn].y));
                rmax1 = fmaxf(rmax1, fmaxf(s[fn].z, s[fn].w));
            }
            rmax0 = fmaxf(rmax0, __shfl_xor_sync(0xffffffffu, rmax0, 1));
            rmax0 = fmaxf(rmax0, __shfl_xor_sync(0xffffffffu, rmax0, 2));
            rmax1 = fmaxf(rmax1, __shfl_xor_sync(0xffffffffu, rmax1, 1));
            rmax1 = fmaxf(rmax1, __shfl_xor_sync(0xffffffffu, rmax1, 2));
            const float mn0 = fmaxf(m0, rmax0), mn1 = fmaxf(m1, rmax1);
            const float al0 = ex2((m0 - mn0) * SCL2E);
            const float al1 = ex2((m1 - mn1) * SCL2E);
            m0 = mn0; m1 = mn1;
            float rs0 = 0.f, rs1 = 0.f;
            #pragma unroll
            for (int fn = 0; fn < 8; fn++) {
                s[fn].x = ex2((s[fn].x - mn0) * SCL2E);
                s[fn].y = ex2((s[fn].y - mn0) * SCL2E);
                s[fn].z = ex2((s[fn].z - mn1) * SCL2E);
                s[fn].w = ex2((s[fn].w - mn1) * SCL2E);
                rs0 += s[fn].x + s[fn].y;
                rs1 += s[fn].z + s[fn].w;
            }
            rs0 += __shfl_xor_sync(0xffffffffu, rs0, 1);
            rs0 += __shfl_xor_sync(0xffffffffu, rs0, 2);
            rs1 += __shfl_xor_sync(0xffffffffu, rs1, 1);
            rs1 += __shfl_xor_sync(0xffffffffu, rs1, 2);
            l0 = l0 * al0 + rs0;
            l1 = l1 * al1 + rs1;
            #pragma unroll
            for (int fn = 0; fn < 8; fn++) {
                o[fn].x *= al0; o[fn].y *= al0;
                o[fn].z *= al1; o[fn].w *= al1;
            }

            // P -> warp-private smem rows (f16)
            #pragma unroll
            for (int fn = 0; fn < 8; fn++) {
                *(__half2*)&Ps[(wm + g) * 72 + fn * 8 + 2 * tg] =
                    __floats2half2_rn(s[fn].x, s[fn].y);
                *(__half2*)&Ps[(wm + g + 8) * 72 + fn * 8 + 2 * tg] =
                    __floats2half2_rn(s[fn].z, s[fn].w);
            }
            __syncwarp();

            // O += P_half @ V_half
            #pragma unroll
            for (int kc = 0; kc < 4; kc++) {
                uint32_t pf[4];
                ldsm4(pf[0], pf[1], pf[2], pf[3], aP + kc * 32);
                #pragma unroll
                for (int cb = 0; cb < 4; cb++) {
                    uint32_t b0, b1, b2, b3;
                    ldsm4(b0, b1, b2, b3,
                          bV + cb * (16 * 272) + (4 * h + kc) * 32);
                    mma16(o[2*cb],   pf, b0, b1);
                    mma16(o[2*cb+1], pf, b2, b3);
                }
            }
            __syncwarp();
        }

        // free this buffer for kt+2, then prefetch
        __syncthreads();
        if (kt + 2 < NT) issueKV(kt + 2, buf);
    }

    // finalize -> g_ao (f16), token-major
    const int b = bh >> 4, h = bh & 15;
    const float inv0 = 1.f / l0, inv1 = 1.f / l1;
    #pragma unroll
    for (int fn = 0; fn < 8; fn++) {
        const int d = fn * 8 + 2 * tg;
        *(__half2*)&g_ao[(size_t)(b * TT + r0g) * CC + h * 64 + d] =
            __floats2half2_rn(o[fn].x * inv0, o[fn].y * inv0);
        *(__half2*)&g_ao[(size_t)(b * TT + r1g) * CC + h * 64 + d] =
            __floats2half2_rn(o[fn].z * inv1, o[fn].w * inv1);
    }
}

// ---------------------------------------------------------------------------
extern "C" void kernel_launch(void* const* d_in, const int* in_sizes, int n_in,
                              void* d_out, int out_size)
{
    const float* x      = (const float*)d_in[0];
    const float* W_qkv  = (const float*)d_in[1];
    const float* b_qkv  = (const float*)d_in[2];
    const float* W_proj = (const float*)d_in[3];
    const float* b_proj = (const float*)d_in[4];
    float* out = (float*)d_out;

    __half* xh;     cudaGetSymbolAddress((void**)&xh,     g_xh);
    __half* wqkvT;  cudaGetSymbolAddress((void**)&wqkvT,  g_wqkvT);
    __half* wprojT; cudaGetSymbolAddress((void**)&wprojT, g_wprojT);
    __half* ao;     cudaGetSymbolAddress((void**)&ao,     g_ao);

    // 0) convert x to f16; transpose+convert weights to f16
    cvt_f32_f16<<<(NTOK*CC/4 + 255)/256, 256>>>(x, xh, NTOK*CC/4);
    transpose_cvt_h<<<dim3(3*CC/32, CC/32), dim3(32, 8)>>>(W_qkv,  wqkvT,  CC, 3*CC);
    transpose_cvt_h<<<dim3(CC/32,   CC/32), dim3(32, 8)>>>(W_proj, wprojT, CC, CC);

    const int gemm_smem = 3 * (ASTG + BSTG);   // 165888
    cudaFuncSetAttribute(mma_gemm<0>, cudaFuncAttributeMaxDynamicSharedMemorySize,
                         gemm_smem);
    cudaFuncSetAttribute(mma_gemm<1>, cudaFuncAttributeMaxDynamicSharedMemorySize,
                         gemm_smem);

    // 1) QKV GEMM (f16 mma, 256x128 tiles, 512 threads) + scatter
    mma_gemm<0><<<dim3(3*CC/128, NTOK/256), 512, gemm_smem>>>(xh, wqkvT, b_qkv,
                                                              nullptr, NTOK, 3*CC, CC);

    // 2) causal flash attention (128-row q tiles, 2 CTAs/SM, ~88 KB smem/CTA)
    const int attn_smem = QB2 + 2 * (KTB + VTB);   // 90112
    cudaFuncSetAttribute(attn_kernel, cudaFuncAttributeMaxDynamicSharedMemorySize,
                         attn_smem);
    attn_kernel<<<dim3(TT/128, BB*HH), 256, attn_smem>>>();

    // 3) output projection (f16 mma, 256x128 tiles, 512 threads)
    mma_gemm<1><<<dim3(CC/128, NTOK/256), 512, gemm_smem>>>(ao, wprojT, b_proj,
                                                            out, NTOK, CC, CC);
}

// round 15
// speedup vs baseline: 1.0579x; 1.0579x over previous
#include <cuda_runtime.h>
#include <cuda_fp16.h>
#include <math.h>
#include <stdint.h>

#define BB 2
#define TT 2048
#define CC 1024
#define HH 16
#define DHD 64
#define NTOK (BB*TT)   // 4096

// Scratch (allocation-free: __device__ globals)
__device__ __half g_xh[NTOK*CC];        // x as f16
__device__ __half g_q[BB*HH*TT*DHD];    // f16, [bh][t][d]
__device__ __half g_k[BB*HH*TT*DHD];    // f16, [bh][t][d]
__device__ __half g_vt[BB*HH*DHD*TT];   // f16, TRANSPOSED [bh][d][t]
__device__ __half g_ao[NTOK*CC];        // attention out f16, token-major
__device__ __half g_wqkvT[3*CC*CC];     // W_qkv^T f16, [3072][1024]
__device__ __half g_wprojT[CC*CC];      // W_proj^T f16, [1024][1024]

// ---------------------------------------------------------------------------
__device__ __forceinline__ float ex2(float x) {
    float r; asm("ex2.approx.f32 %0, %1;" : "=f"(r) : "f"(x)); return r;
}
__device__ __forceinline__ uint32_t smem_u32(const void* p) {
    return (uint32_t)__cvta_generic_to_shared(p);
}
__device__ __forceinline__ void ldsm4(uint32_t& r0, uint32_t& r1, uint32_t& r2,
                                      uint32_t& r3, uint32_t a) {
    asm volatile("ldmatrix.sync.aligned.m8n8.x4.shared.b16 {%0,%1,%2,%3},[%4];"
                 : "=r"(r0), "=r"(r1), "=r"(r2), "=r"(r3) : "r"(a));
}
// f16 MMA: D(f32) += A(f16 m16k16) * B(f16 k16n8)
__device__ __forceinline__ void mma16(float4& d, const uint32_t* a,
                                      uint32_t b0, uint32_t b1) {
    asm volatile("mma.sync.aligned.m16n8k16.row.col.f32.f16.f16.f32 "
                 "{%0,%1,%2,%3},{%4,%5,%6,%7},{%8,%9},{%0,%1,%2,%3};"
                 : "+f"(d.x), "+f"(d.y), "+f"(d.z), "+f"(d.w)
                 : "r"(a[0]), "r"(a[1]), "r"(a[2]), "r"(a[3]), "r"(b0), "r"(b1));
}
__device__ __forceinline__ void cp16(uint32_t s, const void* g) {
    asm volatile("cp.async.cg.shared.global [%0], [%1], 16;" :: "r"(s), "l"(g));
}
__device__ __forceinline__ void cp_commit() {
    asm volatile("cp.async.commit_group;");
}
template<int N>
__device__ __forceinline__ void cp_wait() {
    asm volatile("cp.async.wait_group %0;" :: "n"(N));
}
__device__ __forceinline__ uint32_t h2bits(float a, float b) {
    __half2 h = __floats2half2_rn(a, b);
    return *(uint32_t*)&h;
}

// ---------------------------------------------------------------------------
__global__ void cvt_f32_f16(const float* __restrict__ in, __half* __restrict__ out,
                            int n4)
{
    int i = blockIdx.x * blockDim.x + threadIdx.x;
    if (i < n4) {
        float4 v = ((const float4*)in)[i];
        __half2 h0 = __floats2half2_rn(v.x, v.y);
        __half2 h1 = __floats2half2_rn(v.z, v.w);
        ((uint2*)out)[i] = make_uint2(*(uint32_t*)&h0, *(uint32_t*)&h1);
    }
}

// Transpose + f16-convert: Wt[n*K + k] = f16(W[k*N + n])
__global__ void transpose_cvt_h(const float* __restrict__ W, __half* __restrict__ Wt,
                                int K, int N)
{
    __shared__ float tile[32][33];
    const int n0 = blockIdx.x * 32, k0 = blockIdx.y * 32;
    const int tx = threadIdx.x, ty = threadIdx.y;
    #pragma unroll
    for (int i = ty; i < 32; i += 8)
        tile[i][tx] = W[(size_t)(k0 + i) * N + n0 + tx];
    __syncthreads();
    #pragma unroll
    for (int i = ty; i < 32; i += 8)
        Wt[(size_t)(n0 + i) * K + k0 + tx] = __float2half_rn(tile[tx][i]);
}

// ---------------------------------------------------------------------------
// f16 tensor-core GEMM, 256x128 CTA tile, 512 threads (16 warps of 64x32),
// K-tile = 64 (four k16 sub-steps), 3-stage cp.async ring.
// Rows padded to 144 B (conflict-free LDSM: 144/4=36 = 4 mod 32).
// MODE 0: scatter into g_q/g_k (f16, [bh][t][d]) and g_vt (f16, [bh][d][t])
// MODE 1: fp32 epilogue into Out
// ---------------------------------------------------------------------------
#define ASTG 36864     // A stage: 256 rows x 144 B
#define BSTG 18432     // B stage: 128 rows x 144 B

template<int MODE>
__global__ __launch_bounds__(512, 1)
void mma_gemm(const __half* __restrict__ A, const __half* __restrict__ Bt,
              const float* __restrict__ bias, float* __restrict__ Out,
              int M, int N, int K)
{
    extern __shared__ __align__(16) char dsm[];
    const uint32_t sA = smem_u32(dsm);            // 3 stages A
    const uint32_t sB = sA + 3 * ASTG;            // 3 stages B

    const int row0 = blockIdx.y * 256, col0 = blockIdx.x * 128;
    const int tid = threadIdx.x, lane = tid & 31, wid = tid >> 5;
    const int wm = (wid >> 2) * 64, wn = (wid & 3) * 32;
    const int g = lane >> 2, tg = lane & 3;

    float4 c[4][4];
    #pragma unroll
    for (int i = 0; i < 4; i++)
        #pragma unroll
        for (int j = 0; j < 4; j++) c[i][j] = make_float4(0.f, 0.f, 0.f, 0.f);

    const uint32_t aBase = sA + (wm + (lane & 15)) * 144 + (lane >> 4) * 16;
    const uint32_t bBase = sB + (wn + ((lane >> 4) << 3) + (lane & 7)) * 144
                              + ((lane >> 3) & 1) * 16;

    const int NKT = K / 64;   // 16

    auto issueAB = [&](int kt, int buf) {
        #pragma unroll
        for (int i = 0; i < 4; i++) {
            int idx = tid + i * 512;
            int r = idx >> 3, c8 = idx & 7;
            cp16(sA + buf * ASTG + r * 144 + c8 * 16,
                 A + (size_t)(row0 + r) * K + kt * 64 + c8 * 8);
        }
        #pragma unroll
        for (int i = 0; i < 2; i++) {
            int idx = tid + i * 512;
            int r = idx >> 3, c8 = idx & 7;
            cp16(sB + buf * BSTG + r * 144 + c8 * 16,
                 Bt + (size_t)(col0 + r) * K + kt * 64 + c8 * 8);
        }
        cp_commit();
    };

    issueAB(0, 0); issueAB(1, 1);

    for (int kt = 0; kt < NKT; kt++) {
        if (kt + 1 < NKT) cp_wait<1>();
        else              cp_wait<0>();
        __syncthreads();
        if (kt + 2 < NKT) issueAB(kt + 2, (kt + 2) % 3);

        const int buf = kt % 3;
        const uint32_t aB = aBase + buf * ASTG;
        const uint32_t bB = bBase + buf * BSTG;
        #pragma unroll
        for (int s = 0; s < 4; s++) {
            uint32_t af[4][4], bf[4][2];
            #pragma unroll
            for (int fm = 0; fm < 4; fm++)
                ldsm4(af[fm][0], af[fm][1], af[fm][2], af[fm][3],
                      aB + fm * (16 * 144) + s * 32);
            #pragma unroll
            for (int cb = 0; cb < 2; cb++)
                ldsm4(bf[2*cb][0], bf[2*cb][1], bf[2*cb+1][0], bf[2*cb+1][1],
                      bB + cb * (16 * 144) + s * 32);
            #pragma unroll
            for (int fm = 0; fm < 4; fm++)
                #pragma unroll
                for (int fn = 0; fn < 4; fn++)
                    mma16(c[fm][fn], af[fm], bf[fn][0], bf[fn][1]);
        }
    }

    #pragma unroll
    for (int fm = 0; fm < 4; fm++) {
        #pragma unroll
        for (int fn = 0; fn < 4; fn++) {
            const int m0 = row0 + wm + fm * 16 + g;
            const int m1 = m0 + 8;
            const int n  = col0 + wn + fn * 8 + 2 * tg;
            const float b0v = bias[n], b1v = bias[n + 1];
            float2 lo = make_float2(c[fm][fn].x + b0v, c[fm][fn].y + b1v);
            float2 hi = make_float2(c[fm][fn].z + b0v, c[fm][fn].w + b1v);
            if (MODE == 0) {
                const int which = n >> 10, cc = n & 1023, h = cc >> 6, d = cc & 63;
                const int b = m0 >> 11, t = m0 & 2047;   // same b for m0, m1
                if (which < 2) {
                    __half* dst = (which == 0) ? g_q : g_k;
                    *(__half2*)&dst[((size_t)((b * HH + h) * TT + t)) * DHD + d] =
                        __floats2half2_rn(lo.x, lo.y);
                    *(__half2*)&dst[((size_t)((b * HH + h) * TT + t + 8)) * DHD + d] =
                        __floats2half2_rn(hi.x, hi.y);
                } else {
                    __half* dst = g_vt + (size_t)(b * HH + h) * DHD * TT;
                    dst[(size_t)d * TT + t]           = __float2half_rn(lo.x);
                    dst[(size_t)(d + 1) * TT + t]     = __float2half_rn(lo.y);
                    dst[(size_t)d * TT + t + 8]       = __float2half_rn(hi.x);
                    dst[(size_t)(d + 1) * TT + t + 8] = __float2half_rn(hi.y);
                }
            } else {
                *(float2*)&Out[(size_t)m0 * N + n] = lo;
                *(float2*)&Out[(size_t)m1 * N + n] = hi;
            }
        }
    }
}

// ---------------------------------------------------------------------------
// f16 tensor-core causal flash attention, 128-row q tiles x 128-key tiles,
// 256 threads (8 warps x m16), 2-stage cp.async KV ring.
// P stays IN REGISTERS: the S accumulator fragment pair (s[2k], s[2k+1]),
// packed to half2, is exactly the m16n8k16 A-operand fragment for keys
// 16k..16k+15 — no smem round trip for P.
// K rows 144 B, V^T rows 272 B (both conflict-free for LDSM).
// ---------------------------------------------------------------------------
#define QB2 18432     // Q tile: 128 x 144 B
#define KTB 18432     // K tile: 128 rows x 144 B
#define VTB 17408     // V^T tile: 64 rows x 272 B
#define SCL2E 0.1803368801111204f   // (1/8) * log2(e)

__global__ __launch_bounds__(256)
void attn_kernel()
{
    extern __shared__ __align__(16) char smc[];
    const uint32_t sQ = smem_u32(smc);
    const uint32_t sK = sQ + QB2;               // 2 x KTB
    const uint32_t sV = sK + 2 * KTB;           // 2 x VTB

    const int bh = blockIdx.y;
    const int qt = (int)gridDim.x - 1 - (int)blockIdx.x;  // big tiles first
    const int q0 = qt * 128;
    const int tid = threadIdx.x, lane = tid & 31, wid = tid >> 5;
    const int wm = wid * 16;
    const int g = lane >> 2, tg = lane & 3;

    const __half* Qg = g_q  + (size_t)bh * TT * DHD;
    const __half* Kg = g_k  + (size_t)bh * TT * DHD;
    const __half* Vg = g_vt + (size_t)bh * DHD * TT;

    auto issueKV = [&](int kt, int buf) {
        const int k0 = kt * 128;
        #pragma unroll
        for (int i = 0; i < 4; i++) {
            int idx = tid + i * 256;
            int r = idx >> 3, c8 = idx & 7;
            cp16(sK + buf * KTB + r * 144 + c8 * 16,
                 Kg + (size_t)(k0 + r) * DHD + c8 * 8);
        }
        #pragma unroll
        for (int i = 0; i < 4; i++) {
            int idx = tid + i * 256;
            int r = idx >> 4, c16 = idx & 15;
            cp16(sV + buf * VTB + r * 272 + c16 * 16,
                 Vg + (size_t)r * TT + k0 + c16 * 8);
        }
        cp_commit();
    };

    const int NT = qt + 1;

    // prologue: Q + KV0 (group 0), KV1 (group 1; keys [128,256) always exist)
    #pragma unroll
    for (int i = 0; i < 4; i++) {
        int idx = tid + i * 256;
        int r = idx >> 3, c8 = idx & 7;
        cp16(sQ + r * 144 + c8 * 16, Qg + (size_t)(q0 + r) * DHD + c8 * 8);
    }
    issueKV(0, 0);   // commits Q too (same group)
    issueKV(1, 1);

    // ldmatrix bases
    const uint32_t aQ = sQ + (wm + (lane & 15)) * 144 + (lane >> 4) * 16;
    const uint32_t kOffK = (((lane >> 4) << 3) + (lane & 7)) * 144
                         + ((lane >> 3) & 1) * 16;
    const uint32_t kOffV = (((lane >> 4) << 3) + (lane & 7)) * 272
                         + ((lane >> 3) & 1) * 16;

    uint32_t qf[4][4];
    float4 o[8];
    #pragma unroll
    for (int fn = 0; fn < 8; fn++) o[fn] = make_float4(0.f, 0.f, 0.f, 0.f);
    float m0 = -INFINITY, m1 = -INFINITY, l0 = 0.f, l1 = 0.f;
    const int r0g = q0 + wm + g, r1g = r0g + 8;

    for (int kt = 0; kt < NT; kt++) {
        const int k0 = kt * 128;
        if (kt + 1 < NT) cp_wait<1>();
        else             cp_wait<0>();
        __syncthreads();

        if (kt == 0) {
            #pragma unroll
            for (int kc = 0; kc < 4; kc++)
                ldsm4(qf[kc][0], qf[kc][1], qf[kc][2], qf[kc][3], aQ + kc * 32);
        }

        const int buf = kt & 1;
        const uint32_t bK = sK + buf * KTB + kOffK;
        const uint32_t bV = sV + buf * VTB + kOffV;

        // S = Q K^T  (m16 x n128), raw scores
        float4 s[16];
        #pragma unroll
        for (int fn = 0; fn < 16; fn++) s[fn] = make_float4(0.f, 0.f, 0.f, 0.f);
        #pragma unroll
        for (int kc = 0; kc < 4; kc++) {
            #pragma unroll
            for (int cb = 0; cb < 8; cb++) {
                uint32_t b0, b1, b2, b3;
                ldsm4(b0, b1, b2, b3, bK + cb * (16 * 144) + kc * 32);
                mma16(s[2*cb],   qf[kc], b0, b1);
                mma16(s[2*cb+1], qf[kc], b2, b3);
            }
        }

        // causal mask — q tiles and key tiles align, so only kt == qt masks
        if (kt == NT - 1) {
            #pragma unroll
            for (int fn = 0; fn < 16; fn++) {
                int c0 = k0 + fn * 8 + 2 * tg, c1 = c0 + 1;
                if (c0 > r0g) s[fn].x = -INFINITY;
                if (c1 > r0g) s[fn].y = -INFINITY;
                if (c0 > r1g) s[fn].z = -INFINITY;
                if (c1 > r1g) s[fn].w = -INFINITY;
            }
        }

        // online softmax in base-2 domain (rows g, g+8)
        float rmax0 = -INFINITY, rmax1 = -INFINITY;
        #pragma unroll
        for (int fn = 0; fn < 16; fn++) {
            rmax0 = fmaxf(rmax0, fmaxf(s[fn].x, s[fn].y));
            rmax1 = fmaxf(rmax1, fmaxf(s[fn].z, s[fn].w));
        }
        rmax0 = fmaxf(rmax0, __shfl_xor_sync(0xffffffffu, rmax0, 1));
        rmax0 = fmaxf(rmax0, __shfl_xor_sync(0xffffffffu, rmax0, 2));
        rmax1 = fmaxf(rmax1, __shfl_xor_sync(0xffffffffu, rmax1, 1));
        rmax1 = fmaxf(rmax1, __shfl_xor_sync(0xffffffffu, rmax1, 2));
        const float mn0 = fmaxf(m0, rmax0), mn1 = fmaxf(m1, rmax1);
        const float al0 = ex2((m0 - mn0) * SCL2E), al1 = ex2((m1 - mn1) * SCL2E);
        m0 = mn0; m1 = mn1;
        float rs0 = 0.f, rs1 = 0.f;
        #pragma unroll
        for (int fn = 0; fn < 16; fn++) {
            s[fn].x = ex2((s[fn].x - mn0) * SCL2E);
            s[fn].y = ex2((s[fn].y - mn0) * SCL2E);
            s[fn].z = ex2((s[fn].z - mn1) * SCL2E);
            s[fn].w = ex2((s[fn].w - mn1) * SCL2E);
            rs0 += s[fn].x + s[fn].y;
            rs1 += s[fn].z + s[fn].w;
        }
        rs0 += __shfl_xor_sync(0xffffffffu, rs0, 1);
        rs0 += __shfl_xor_sync(0xffffffffu, rs0, 2);
        rs1 += __shfl_xor_sync(0xffffffffu, rs1, 1);
        rs1 += __shfl_xor_sync(0xffffffffu, rs1, 2);
        l0 = l0 * al0 + rs0;
        l1 = l1 * al1 + rs1;
        #pragma unroll
        for (int fn = 0; fn < 8; fn++) {
            o[fn].x *= al0; o[fn].y *= al0;
            o[fn].z *= al1; o[fn].w *= al1;
        }

        // O += P @ V with P taken straight from the S accumulator registers:
        // A-frag(keys 16k..16k+15) = {h2(s[2k].xy), h2(s[2k].zw),
        //                              h2(s[2k+1].xy), h2(s[2k+1].zw)}
        #pragma unroll
        for (int kc = 0; kc < 8; kc++) {
            uint32_t pf[4];
            pf[0] = h2bits(s[2*kc].x,   s[2*kc].y);
            pf[1] = h2bits(s[2*kc].z,   s[2*kc].w);
            pf[2] = h2bits(s[2*kc+1].x, s[2*kc+1].y);
            pf[3] = h2bits(s[2*kc+1].z, s[2*kc+1].w);
            #pragma unroll
            for (int cb = 0; cb < 4; cb++) {
                uint32_t b0, b1, b2, b3;
                ldsm4(b0, b1, b2, b3, bV + cb * (16 * 272) + kc * 32);
                mma16(o[2*cb],   pf, b0, b1);
                mma16(o[2*cb+1], pf, b2, b3);
            }
        }

        // free this buffer for kt+2, then prefetch
        __syncthreads();
        if (kt + 2 < NT) issueKV(kt + 2, buf);
    }

    // finalize -> g_ao (f16), token-major
    const int b = bh >> 4, h = bh & 15;
    const float inv0 = 1.f / l0, inv1 = 1.f / l1;
    #pragma unroll
    for (int fn = 0; fn < 8; fn++) {
        const int d = fn * 8 + 2 * tg;
        *(__half2*)&g_ao[(size_t)(b * TT + r0g) * CC + h * 64 + d] =
            __floats2half2_rn(o[fn].x * inv0, o[fn].y * inv0);
        *(__half2*)&g_ao[(size_t)(b * TT + r1g) * CC + h * 64 + d] =
            __floats2half2_rn(o[fn].z * inv1, o[fn].w * inv1);
    }
}

// ---------------------------------------------------------------------------
extern "C" void kernel_launch(void* const* d_in, const int* in_sizes, int n_in,
                              void* d_out, int out_size)
{
    const float* x      = (const float*)d_in[0];
    const float* W_qkv  = (const float*)d_in[1];
    const float* b_qkv  = (const float*)d_in[2];
    const float* W_proj = (const float*)d_in[3];
    const float* b_proj = (const float*)d_in[4];
    float* out = (float*)d_out;

    __half* xh;     cudaGetSymbolAddress((void**)&xh,     g_xh);
    __half* wqkvT;  cudaGetSymbolAddress((void**)&wqkvT,  g_wqkvT);
    __half* wprojT; cudaGetSymbolAddress((void**)&wprojT, g_wprojT);
    __half* ao;     cudaGetSymbolAddress((void**)&ao,     g_ao);

    // 0) convert x to f16; transpose+convert weights to f16
    cvt_f32_f16<<<(NTOK*CC/4 + 255)/256, 256>>>(x, xh, NTOK*CC/4);
    transpose_cvt_h<<<dim3(3*CC/32, CC/32), dim3(32, 8)>>>(W_qkv,  wqkvT,  CC, 3*CC);
    transpose_cvt_h<<<dim3(CC/32,   CC/32), dim3(32, 8)>>>(W_proj, wprojT, CC, CC);

    const int gemm_smem = 3 * (ASTG + BSTG);   // 165888
    cudaFuncSetAttribute(mma_gemm<0>, cudaFuncAttributeMaxDynamicSharedMemorySize,
                         gemm_smem);
    cudaFuncSetAttribute(mma_gemm<1>, cudaFuncAttributeMaxDynamicSharedMemorySize,
                         gemm_smem);

    // 1) QKV GEMM (f16 mma, 256x128 tiles, 512 threads) + scatter
    mma_gemm<0><<<dim3(3*CC/128, NTOK/256), 512, gemm_smem>>>(xh, wqkvT, b_qkv,
                                                              nullptr, NTOK, 3*CC, CC);

    // 2) causal flash attention (128-row q tiles, register-resident P)
    const int attn_smem = QB2 + 2 * (KTB + VTB);   // 90112
    cudaFuncSetAttribute(attn_kernel, cudaFuncAttributeMaxDynamicSharedMemorySize,
                         attn_smem);
    attn_kernel<<<dim3(TT/128, BB*HH), 256, attn_smem>>>();

    // 3) output projection (f16 mma, 256x128 tiles, 512 threads)
    mma_gemm<1><<<dim3(CC/128, NTOK/256), 512, gemm_smem>>>(ao, wprojT, b_proj,
                                                            out, NTOK, CC, CC);
}

// round 16
// speedup vs baseline: 1.0781x; 1.0191x over previous
#include <cuda_runtime.h>
#include <cuda_fp16.h>
#include <math.h>
#include <stdint.h>

#define BB 2
#define TT 2048
#define CC 1024
#define HH 16
#define DHD 64
#define NTOK (BB*TT)   // 4096

// Scratch (allocation-free: __device__ globals)
__device__ __half g_xh[NTOK*CC];        // x as f16
__device__ __half g_q[BB*HH*TT*DHD];    // f16, [bh][t][d]
__device__ __half g_k[BB*HH*TT*DHD];    // f16, [bh][t][d]
__device__ __half g_vt[BB*HH*DHD*TT];   // f16, TRANSPOSED [bh][d][t]
__device__ __half g_ao[NTOK*CC];        // attention out f16, token-major
__device__ __half g_wqkvT[3*CC*CC];     // W_qkv^T f16, [3072][1024]
__device__ __half g_wprojT[CC*CC];      // W_proj^T f16, [1024][1024]

// ---------------------------------------------------------------------------
__device__ __forceinline__ float ex2(float x) {
    float r; asm("ex2.approx.f32 %0, %1;" : "=f"(r) : "f"(x)); return r;
}
__device__ __forceinline__ uint32_t ex2h2(uint32_t x) {
    uint32_t r; asm("ex2.approx.f16x2 %0, %1;" : "=r"(r) : "r"(x)); return r;
}
__device__ __forceinline__ uint32_t smem_u32(const void* p) {
    return (uint32_t)__cvta_generic_to_shared(p);
}
__device__ __forceinline__ void ldsm4(uint32_t& r0, uint32_t& r1, uint32_t& r2,
                                      uint32_t& r3, uint32_t a) {
    asm volatile("ldmatrix.sync.aligned.m8n8.x4.shared.b16 {%0,%1,%2,%3},[%4];"
                 : "=r"(r0), "=r"(r1), "=r"(r2), "=r"(r3) : "r"(a));
}
// f16 MMA: D(f32) += A(f16 m16k16) * B(f16 k16n8)
__device__ __forceinline__ void mma16(float4& d, const uint32_t* a,
                                      uint32_t b0, uint32_t b1) {
    asm volatile("mma.sync.aligned.m16n8k16.row.col.f32.f16.f16.f32 "
                 "{%0,%1,%2,%3},{%4,%5,%6,%7},{%8,%9},{%0,%1,%2,%3};"
                 : "+f"(d.x), "+f"(d.y), "+f"(d.z), "+f"(d.w)
                 : "r"(a[0]), "r"(a[1]), "r"(a[2]), "r"(a[3]), "r"(b0), "r"(b1));
}
__device__ __forceinline__ void cp16(uint32_t s, const void* g) {
    asm volatile("cp.async.cg.shared.global [%0], [%1], 16;" :: "r"(s), "l"(g));
}
__device__ __forceinline__ void cp_commit() {
    asm volatile("cp.async.commit_group;");
}
template<int N>
__device__ __forceinline__ void cp_wait() {
    asm volatile("cp.async.wait_group %0;" :: "n"(N));
}
__device__ __forceinline__ uint32_t pack_f16x2(float a, float b) {
    __half2 h = __floats2half2_rn(a, b);
    return *(uint32_t*)&h;
}

// ---------------------------------------------------------------------------
__global__ void cvt_f32_f16(const float* __restrict__ in, __half* __restrict__ out,
                            int n4)
{
    int i = blockIdx.x * blockDim.x + threadIdx.x;
    if (i < n4) {
        float4 v = ((const float4*)in)[i];
        __half2 h0 = __floats2half2_rn(v.x, v.y);
        __half2 h1 = __floats2half2_rn(v.z, v.w);
        ((uint2*)out)[i] = make_uint2(*(uint32_t*)&h0, *(uint32_t*)&h1);
    }
}

// Transpose + f16-convert: Wt[n*K + k] = f16(W[k*N + n])
__global__ void transpose_cvt_h(const float* __restrict__ W, __half* __restrict__ Wt,
                                int K, int N)
{
    __shared__ float tile[32][33];
    const int n0 = blockIdx.x * 32, k0 = blockIdx.y * 32;
    const int tx = threadIdx.x, ty = threadIdx.y;
    #pragma unroll
    for (int i = ty; i < 32; i += 8)
        tile[i][tx] = W[(size_t)(k0 + i) * N + n0 + tx];
    __syncthreads();
    #pragma unroll
    for (int i = ty; i < 32; i += 8)
        Wt[(size_t)(n0 + i) * K + k0 + tx] = __float2half_rn(tile[tx][i]);
}

// ---------------------------------------------------------------------------
// f16 tensor-core GEMM, 256x128 CTA tile, 512 threads (16 warps of 64x32),
// K-tile = 64 (four k16 sub-steps), 3-stage cp.async ring.
// Rows padded to 144 B (conflict-free LDSM: 144/4=36 = 4 mod 32).
// MODE 0: scatter into g_q/g_k (f16, [bh][t][d]) and g_vt (f16, [bh][d][t])
// MODE 1: fp32 epilogue into Out
// ---------------------------------------------------------------------------
#define ASTG 36864     // A stage: 256 rows x 144 B
#define BSTG 18432     // B stage: 128 rows x 144 B

template<int MODE>
__global__ __launch_bounds__(512, 1)
void mma_gemm(const __half* __restrict__ A, const __half* __restrict__ Bt,
              const float* __restrict__ bias, float* __restrict__ Out,
              int M, int N, int K)
{
    extern __shared__ __align__(16) char dsm[];
    const uint32_t sA = smem_u32(dsm);            // 3 stages A
    const uint32_t sB = sA + 3 * ASTG;            // 3 stages B

    const int row0 = blockIdx.y * 256, col0 = blockIdx.x * 128;
    const int tid = threadIdx.x, lane = tid & 31, wid = tid >> 5;
    const int wm = (wid >> 2) * 64, wn = (wid & 3) * 32;
    const int g = lane >> 2, tg = lane & 3;

    float4 c[4][4];
    #pragma unroll
    for (int i = 0; i < 4; i++)
        #pragma unroll
        for (int j = 0; j < 4; j++) c[i][j] = make_float4(0.f, 0.f, 0.f, 0.f);

    const uint32_t aBase = sA + (wm + (lane & 15)) * 144 + (lane >> 4) * 16;
    const uint32_t bBase = sB + (wn + ((lane >> 4) << 3) + (lane & 7)) * 144
                              + ((lane >> 3) & 1) * 16;

    const int NKT = K / 64;   // 16

    auto issueAB = [&](int kt, int buf) {
        #pragma unroll
        for (int i = 0; i < 4; i++) {
            int idx = tid + i * 512;
            int r = idx >> 3, c8 = idx & 7;
            cp16(sA + buf * ASTG + r * 144 + c8 * 16,
                 A + (size_t)(row0 + r) * K + kt * 64 + c8 * 8);
        }
        #pragma unroll
        for (int i = 0; i < 2; i++) {
            int idx = tid + i * 512;
            int r = idx >> 3, c8 = idx & 7;
            cp16(sB + buf * BSTG + r * 144 + c8 * 16,
                 Bt + (size_t)(col0 + r) * K + kt * 64 + c8 * 8);
        }
        cp_commit();
    };

    issueAB(0, 0); issueAB(1, 1);

    for (int kt = 0; kt < NKT; kt++) {
        if (kt + 1 < NKT) cp_wait<1>();
        else              cp_wait<0>();
        __syncthreads();
        if (kt + 2 < NKT) issueAB(kt + 2, (kt + 2) % 3);

        const int buf = kt % 3;
        const uint32_t aB = aBase + buf * ASTG;
        const uint32_t bB = bBase + buf * BSTG;
        #pragma unroll
        for (int s = 0; s < 4; s++) {
            uint32_t af[4][4], bf[4][2];
            #pragma unroll
            for (int fm = 0; fm < 4; fm++)
                ldsm4(af[fm][0], af[fm][1], af[fm][2], af[fm][3],
                      aB + fm * (16 * 144) + s * 32);
            #pragma unroll
            for (int cb = 0; cb < 2; cb++)
                ldsm4(bf[2*cb][0], bf[2*cb][1], bf[2*cb+1][0], bf[2*cb+1][1],
                      bB + cb * (16 * 144) + s * 32);
            #pragma unroll
            for (int fm = 0; fm < 4; fm++)
                #pragma unroll
                for (int fn = 0; fn < 4; fn++)
                    mma16(c[fm][fn], af[fm], bf[fn][0], bf[fn][1]);
        }
    }

    #pragma unroll
    for (int fm = 0; fm < 4; fm++) {
        #pragma unroll
        for (int fn = 0; fn < 4; fn++) {
            const int m0 = row0 + wm + fm * 16 + g;
            const int m1 = m0 + 8;
            const int n  = col0 + wn + fn * 8 + 2 * tg;
            const float b0v = bias[n], b1v = bias[n + 1];
            float2 lo = make_float2(c[fm][fn].x + b0v, c[fm][fn].y + b1v);
            float2 hi = make_float2(c[fm][fn].z + b0v, c[fm][fn].w + b1v);
            if (MODE == 0) {
                const int which = n >> 10, cc = n & 1023, h = cc >> 6, d = cc & 63;
                const int b = m0 >> 11, t = m0 & 2047;   // same b for m0, m1
                if (which < 2) {
                    __half* dst = (which == 0) ? g_q : g_k;
                    *(__half2*)&dst[((size_t)((b * HH + h) * TT + t)) * DHD + d] =
                        __floats2half2_rn(lo.x, lo.y);
                    *(__half2*)&dst[((size_t)((b * HH + h) * TT + t + 8)) * DHD + d] =
                        __floats2half2_rn(hi.x, hi.y);
                } else {
                    __half* dst = g_vt + (size_t)(b * HH + h) * DHD * TT;
                    dst[(size_t)d * TT + t]           = __float2half_rn(lo.x);
                    dst[(size_t)(d + 1) * TT + t]     = __float2half_rn(lo.y);
                    dst[(size_t)d * TT + t + 8]       = __float2half_rn(hi.x);
                    dst[(size_t)(d + 1) * TT + t + 8] = __float2half_rn(hi.y);
                }
            } else {
                *(float2*)&Out[(size_t)m0 * N + n] = lo;
                *(float2*)&Out[(size_t)m1 * N + n] = hi;
            }
        }
    }
}

// ---------------------------------------------------------------------------
// f16 tensor-core causal flash attention, 128-row q tiles x 128-key tiles,
// 256 threads (8 warps x m16), 2-stage cp.async KV ring.
// P stays IN REGISTERS (S fragment == P A-fragment after f16 pack), the
// exponent is taken with ex2.approx.f16x2 (half the MUFU ops, pack fused),
// and the row-sum l is computed BY THE TENSOR PIPE via a ones-row appended
// to V^T (row d=64): l accumulates in a 9th output fragment, rescaled by
// alpha exactly like O. K rows 144 B, V^T rows 272 B (conflict-free LDSM).
// ---------------------------------------------------------------------------
#define QB2 18432     // Q tile: 128 x 144 B
#define KTB 18432     // K tile: 128 rows x 144 B
#define VTB 21760     // V^T tile: 80 rows (64 d + ones row + 15 zero) x 272 B
#define SCL2E 0.1803368801111204f   // (1/8) * log2(e)

__global__ __launch_bounds__(256)
void attn_kernel()
{
    extern __shared__ __align__(16) char smc[];
    const uint32_t sQ = smem_u32(smc);
    const uint32_t sK = sQ + QB2;               // 2 x KTB
    const uint32_t sV = sK + 2 * KTB;           // 2 x VTB

    const int bh = blockIdx.y;
    const int qt = (int)gridDim.x - 1 - (int)blockIdx.x;  // big tiles first
    const int q0 = qt * 128;
    const int tid = threadIdx.x, lane = tid & 31, wid = tid >> 5;
    const int wm = wid * 16;
    const int g = lane >> 2, tg = lane & 3;

    const __half* Qg = g_q  + (size_t)bh * TT * DHD;
    const __half* Kg = g_k  + (size_t)bh * TT * DHD;
    const __half* Vg = g_vt + (size_t)bh * DHD * TT;

    auto issueKV = [&](int kt, int buf) {
        const int k0 = kt * 128;
        #pragma unroll
        for (int i = 0; i < 4; i++) {
            int idx = tid + i * 256;
            int r = idx >> 3, c8 = idx & 7;
            cp16(sK + buf * KTB + r * 144 + c8 * 16,
                 Kg + (size_t)(k0 + r) * DHD + c8 * 8);
        }
        #pragma unroll
        for (int i = 0; i < 4; i++) {
            int idx = tid + i * 256;
            int r = idx >> 4, c16 = idx & 15;
            cp16(sV + buf * VTB + r * 272 + c16 * 16,
                 Vg + (size_t)r * TT + k0 + c16 * 8);
        }
        cp_commit();
    };

    const int NT = qt + 1;

    // prologue: Q + KV0 (group 0), KV1 (group 1; keys [128,256) always exist)
    #pragma unroll
    for (int i = 0; i < 4; i++) {
        int idx = tid + i * 256;
        int r = idx >> 3, c8 = idx & 7;
        cp16(sQ + r * 144 + c8 * 16, Qg + (size_t)(q0 + r) * DHD + c8 * 8);
    }
    issueKV(0, 0);   // commits Q too (same group)
    issueKV(1, 1);

    // fill the static rows 64..79 of both V^T buffers: row 64 = ones (the
    // l-accumulator column), rows 65..79 = zeros. Never touched by issueKV.
    for (int i = tid; i < 2 * 16 * 68; i += 256) {
        int b   = i / (16 * 68);
        int rem = i % (16 * 68);
        int r = rem / 68, c4 = rem % 68;
        uint32_t v = (r == 0) ? 0x3C003C00u : 0u;   // half2(1,1) : 0
        *(uint32_t*)(smc + QB2 + 2 * KTB + b * VTB + (64 + r) * 272 + c4 * 4) = v;
    }

    // ldmatrix bases
    const uint32_t aQ = sQ + (wm + (lane & 15)) * 144 + (lane >> 4) * 16;
    const uint32_t kOffK = (((lane >> 4) << 3) + (lane & 7)) * 144
                         + ((lane >> 3) & 1) * 16;
    const uint32_t kOffV = (((lane >> 4) << 3) + (lane & 7)) * 272
                         + ((lane >> 3) & 1) * 16;

    uint32_t qf[4][4];
    float4 o[8], oe;
    #pragma unroll
    for (int fn = 0; fn < 8; fn++) o[fn] = make_float4(0.f, 0.f, 0.f, 0.f);
    oe = make_float4(0.f, 0.f, 0.f, 0.f);
    float m0 = -INFINITY, m1 = -INFINITY;
    const int r0g = q0 + wm + g, r1g = r0g + 8;

    for (int kt = 0; kt < NT; kt++) {
        const int k0 = kt * 128;
        if (kt + 1 < NT) cp_wait<1>();
        else             cp_wait<0>();
        __syncthreads();

        if (kt == 0) {
            #pragma unroll
            for (int kc = 0; kc < 4; kc++)
                ldsm4(qf[kc][0], qf[kc][1], qf[kc][2], qf[kc][3], aQ + kc * 32);
        }

        const int buf = kt & 1;
        const uint32_t bK = sK + buf * KTB + kOffK;
        const uint32_t bV = sV + buf * VTB + kOffV;

        // S = Q K^T  (m16 x n128), raw scores
        float4 s[16];
        #pragma unroll
        for (int fn = 0; fn < 16; fn++) s[fn] = make_float4(0.f, 0.f, 0.f, 0.f);
        #pragma unroll
        for (int kc = 0; kc < 4; kc++) {
            #pragma unroll
            for (int cb = 0; cb < 8; cb++) {
                uint32_t b0, b1, b2, b3;
                ldsm4(b0, b1, b2, b3, bK + cb * (16 * 144) + kc * 32);
                mma16(s[2*cb],   qf[kc], b0, b1);
                mma16(s[2*cb+1], qf[kc], b2, b3);
            }
        }

        // causal mask — q tiles and key tiles align, so only kt == qt masks
        if (kt == NT - 1) {
            #pragma unroll
            for (int fn = 0; fn < 16; fn++) {
                int c0 = k0 + fn * 8 + 2 * tg, c1 = c0 + 1;
                if (c0 > r0g) s[fn].x = -INFINITY;
                if (c1 > r0g) s[fn].y = -INFINITY;
                if (c0 > r1g) s[fn].z = -INFINITY;
                if (c1 > r1g) s[fn].w = -INFINITY;
            }
        }

        // row max (rows g, g+8)
        float rmax0 = -INFINITY, rmax1 = -INFINITY;
        #pragma unroll
        for (int fn = 0; fn < 16; fn++) {
            rmax0 = fmaxf(rmax0, fmaxf(s[fn].x, s[fn].y));
            rmax1 = fmaxf(rmax1, fmaxf(s[fn].z, s[fn].w));
        }
        rmax0 = fmaxf(rmax0, __shfl_xor_sync(0xffffffffu, rmax0, 1));
        rmax0 = fmaxf(rmax0, __shfl_xor_sync(0xffffffffu, rmax0, 2));
        rmax1 = fmaxf(rmax1, __shfl_xor_sync(0xffffffffu, rmax1, 1));
        rmax1 = fmaxf(rmax1, __shfl_xor_sync(0xffffffffu, rmax1, 2));
        const float mn0 = fmaxf(m0, rmax0), mn1 = fmaxf(m1, rmax1);
        const float al0 = ex2((m0 - mn0) * SCL2E), al1 = ex2((m1 - mn1) * SCL2E);
        m0 = mn0; m1 = mn1;
        const float mns0 = mn0 * SCL2E, mns1 = mn1 * SCL2E;

        // exponent in f16x2 domain — result is directly the packed P fragment
        uint32_t pf[32];
        #pragma unroll
        for (int fn = 0; fn < 16; fn++) {
            uint32_t ux = pack_f16x2(fmaf(s[fn].x, SCL2E, -mns0),
                                     fmaf(s[fn].y, SCL2E, -mns0));
            uint32_t uz = pack_f16x2(fmaf(s[fn].z, SCL2E, -mns1),
                                     fmaf(s[fn].w, SCL2E, -mns1));
            pf[2*fn]   = ex2h2(ux);
            pf[2*fn+1] = ex2h2(uz);
        }

        // rescale O and the l-accumulator fragment
        #pragma unroll
        for (int fn = 0; fn < 8; fn++) {
            o[fn].x *= al0; o[fn].y *= al0;
            o[fn].z *= al1; o[fn].w *= al1;
        }
        oe.x *= al0; oe.z *= al1;

        // O += P @ V ; l += P @ ones  (5th cb block = ones row at d=64)
        #pragma unroll
        for (int kc = 0; kc < 8; kc++) {
            const uint32_t* pa = &pf[4*kc];
            #pragma unroll
            for (int cb = 0; cb < 4; cb++) {
                uint32_t b0, b1, b2, b3;
                ldsm4(b0, b1, b2, b3, bV + cb * (16 * 272) + kc * 32);
                mma16(o[2*cb],   pa, b0, b1);
                mma16(o[2*cb+1], pa, b2, b3);
            }
            uint32_t e0, e1, e2, e3;
            ldsm4(e0, e1, e2, e3, bV + 4 * (16 * 272) + kc * 32);
            mma16(oe, pa, e0, e1);
        }

        // free this buffer for kt+2, then prefetch
        __syncthreads();
        if (kt + 2 < NT) issueKV(kt + 2, buf);
    }

    // l lives in column 64 (frag col 0) -> tg==0 lanes; broadcast in quad
    const int src = lane & ~3;
    const float l0 = __shfl_sync(0xffffffffu, oe.x, src);
    const float l1 = __shfl_sync(0xffffffffu, oe.z, src);

    // finalize -> g_ao (f16), token-major
    const int b = bh >> 4, h = bh & 15;
    const float inv0 = 1.f / l0, inv1 = 1.f / l1;
    #pragma unroll
    for (int fn = 0; fn < 8; fn++) {
        const int d = fn * 8 + 2 * tg;
        *(__half2*)&g_ao[(size_t)(b * TT + r0g) * CC + h * 64 + d] =
            __floats2half2_rn(o[fn].x * inv0, o[fn].y * inv0);
        *(__half2*)&g_ao[(size_t)(b * TT + r1g) * CC + h * 64 + d] =
            __floats2half2_rn(o[fn].z * inv1, o[fn].w * inv1);
    }
}

// ---------------------------------------------------------------------------
extern "C" void kernel_launch(void* const* d_in, const int* in_sizes, int n_in,
                              void* d_out, int out_size)
{
    const float* x      = (const float*)d_in[0];
    const float* W_qkv  = (const float*)d_in[1];
    const float* b_qkv  = (const float*)d_in[2];
    const float* W_proj = (const float*)d_in[3];
    const float* b_proj = (const float*)d_in[4];
    float* out = (float*)d_out;

    __half* xh;     cudaGetSymbolAddress((void**)&xh,     g_xh);
    __half* wqkvT;  cudaGetSymbolAddress((void**)&wqkvT,  g_wqkvT);
    __half* wprojT; cudaGetSymbolAddress((void**)&wprojT, g_wprojT);
    __half* ao;     cudaGetSymbolAddress((void**)&ao,     g_ao);

    // 0) convert x to f16; transpose+convert weights to f16
    cvt_f32_f16<<<(NTOK*CC/4 + 255)/256, 256>>>(x, xh, NTOK*CC/4);
    transpose_cvt_h<<<dim3(3*CC/32, CC/32), dim3(32, 8)>>>(W_qkv,  wqkvT,  CC, 3*CC);
    transpose_cvt_h<<<dim3(CC/32,   CC/32), dim3(32, 8)>>>(W_proj, wprojT, CC, CC);

    const int gemm_smem = 3 * (ASTG + BSTG);   // 165888
    cudaFuncSetAttribute(mma_gemm<0>, cudaFuncAttributeMaxDynamicSharedMemorySize,
                         gemm_smem);
    cudaFuncSetAttribute(mma_gemm<1>, cudaFuncAttributeMaxDynamicSharedMemorySize,
                         gemm_smem);

    // 1) QKV GEMM (f16 mma, 256x128 tiles, 512 threads) + scatter
    mma_gemm<0><<<dim3(3*CC/128, NTOK/256), 512, gemm_smem>>>(xh, wqkvT, b_qkv,
                                                              nullptr, NTOK, 3*CC, CC);

    // 2) causal flash attention (register P, f16x2 ex2, MMA row-sum)
    const int attn_smem = QB2 + 2 * KTB + 2 * VTB;   // 98816
    cudaFuncSetAttribute(attn_kernel, cudaFuncAttributeMaxDynamicSharedMemorySize,
                         attn_smem);
    attn_kernel<<<dim3(TT/128, BB*HH), 256, attn_smem>>>();

    // 3) output projection (f16 mma, 256x128 tiles, 512 threads)
    mma_gemm<1><<<dim3(CC/128, NTOK/256), 512, gemm_smem>>>(ao, wprojT, b_proj,
                                                            out, NTOK, CC, CC);
}

// round 17
// speedup vs baseline: 1.0903x; 1.0113x over previous
#include <cuda_runtime.h>
#include <cuda_fp16.h>
#include <math.h>
#include <stdint.h>

#define BB 2
#define TT 2048
#define CC 1024
#define HH 16
#define DHD 64
#define NTOK (BB*TT)   // 4096

// Scratch (allocation-free: __device__ globals)
__device__ __half g_xh[NTOK*CC];        // x as f16
__device__ __half g_q[BB*HH*TT*DHD];    // f16, [bh][t][d]
__device__ __half g_k[BB*HH*TT*DHD];    // f16, [bh][t][d]
__device__ __half g_vt[BB*HH*DHD*TT];   // f16, TRANSPOSED [bh][d][t]
__device__ __half g_ao[NTOK*CC];        // attention out f16, token-major
__device__ __half g_wqkvT[3*CC*CC];     // W_qkv^T f16, [3072][1024]
__device__ __half g_wprojT[CC*CC];      // W_proj^T f16, [1024][1024]

// ---------------------------------------------------------------------------
__device__ __forceinline__ float ex2(float x) {
    float r; asm("ex2.approx.f32 %0, %1;" : "=f"(r) : "f"(x)); return r;
}
__device__ __forceinline__ uint32_t ex2h2(uint32_t x) {
    uint32_t r; asm("ex2.approx.f16x2 %0, %1;" : "=r"(r) : "r"(x)); return r;
}
__device__ __forceinline__ uint32_t smem_u32(const void* p) {
    return (uint32_t)__cvta_generic_to_shared(p);
}
__device__ __forceinline__ void ldsm4(uint32_t& r0, uint32_t& r1, uint32_t& r2,
                                      uint32_t& r3, uint32_t a) {
    asm volatile("ldmatrix.sync.aligned.m8n8.x4.shared.b16 {%0,%1,%2,%3},[%4];"
                 : "=r"(r0), "=r"(r1), "=r"(r2), "=r"(r3) : "r"(a));
}
// f16 MMA: D(f32) += A(f16 m16k16) * B(f16 k16n8)
__device__ __forceinline__ void mma16(float4& d, const uint32_t* a,
                                      uint32_t b0, uint32_t b1) {
    asm volatile("mma.sync.aligned.m16n8k16.row.col.f32.f16.f16.f32 "
                 "{%0,%1,%2,%3},{%4,%5,%6,%7},{%8,%9},{%0,%1,%2,%3};"
                 : "+f"(d.x), "+f"(d.y), "+f"(d.z), "+f"(d.w)
                 : "r"(a[0]), "r"(a[1]), "r"(a[2]), "r"(a[3]), "r"(b0), "r"(b1));
}
__device__ __forceinline__ void cp16(uint32_t s, const void* g) {
    asm volatile("cp.async.cg.shared.global [%0], [%1], 16;" :: "r"(s), "l"(g));
}
__device__ __forceinline__ void cp_commit() {
    asm volatile("cp.async.commit_group;");
}
template<int N>
__device__ __forceinline__ void cp_wait() {
    asm volatile("cp.async.wait_group %0;" :: "n"(N));
}
__device__ __forceinline__ uint32_t pack_f16x2(float a, float b) {
    __half2 h = __floats2half2_rn(a, b);
    return *(uint32_t*)&h;
}

// ---------------------------------------------------------------------------
__global__ void cvt_f32_f16(const float* __restrict__ in, __half* __restrict__ out,
                            int n4)
{
    int i = blockIdx.x * blockDim.x + threadIdx.x;
    if (i < n4) {
        float4 v = ((const float4*)in)[i];
        __half2 h0 = __floats2half2_rn(v.x, v.y);
        __half2 h1 = __floats2half2_rn(v.z, v.w);
        ((uint2*)out)[i] = make_uint2(*(uint32_t*)&h0, *(uint32_t*)&h1);
    }
}

// Transpose + f16-convert: Wt[n*K + k] = f16(W[k*N + n])
__global__ void transpose_cvt_h(const float* __restrict__ W, __half* __restrict__ Wt,
                                int K, int N)
{
    __shared__ float tile[32][33];
    const int n0 = blockIdx.x * 32, k0 = blockIdx.y * 32;
    const int tx = threadIdx.x, ty = threadIdx.y;
    #pragma unroll
    for (int i = ty; i < 32; i += 8)
        tile[i][tx] = W[(size_t)(k0 + i) * N + n0 + tx];
    __syncthreads();
    #pragma unroll
    for (int i = ty; i < 32; i += 8)
        Wt[(size_t)(n0 + i) * K + k0 + tx] = __float2half_rn(tile[tx][i]);
}

// ---------------------------------------------------------------------------
// f16 tensor-core GEMM, 256x128 CTA tile, 512 threads (16 warps of 64x32),
// K-tile = 64 (four k16 sub-steps), 3-stage cp.async ring.
// Rows padded to 144 B (conflict-free LDSM: 144/4=36 = 4 mod 32).
// MODE 0: scatter into g_q/g_k (f16, [bh][t][d]) and g_vt (f16, [bh][d][t])
// MODE 1: fp32 epilogue into Out
// ---------------------------------------------------------------------------
#define ASTG 36864     // A stage: 256 rows x 144 B
#define BSTG 18432     // B stage: 128 rows x 144 B

template<int MODE>
__global__ __launch_bounds__(512, 1)
void mma_gemm(const __half* __restrict__ A, const __half* __restrict__ Bt,
              const float* __restrict__ bias, float* __restrict__ Out,
              int M, int N, int K)
{
    extern __shared__ __align__(16) char dsm[];
    const uint32_t sA = smem_u32(dsm);            // 3 stages A
    const uint32_t sB = sA + 3 * ASTG;            // 3 stages B

    const int row0 = blockIdx.y * 256, col0 = blockIdx.x * 128;
    const int tid = threadIdx.x, lane = tid & 31, wid = tid >> 5;
    const int wm = (wid >> 2) * 64, wn = (wid & 3) * 32;
    const int g = lane >> 2, tg = lane & 3;

    float4 c[4][4];
    #pragma unroll
    for (int i = 0; i < 4; i++)
        #pragma unroll
        for (int j = 0; j < 4; j++) c[i][j] = make_float4(0.f, 0.f, 0.f, 0.f);

    const uint32_t aBase = sA + (wm + (lane & 15)) * 144 + (lane >> 4) * 16;
    const uint32_t bBase = sB + (wn + ((lane >> 4) << 3) + (lane & 7)) * 144
                              + ((lane >> 3) & 1) * 16;

    const int NKT = K / 64;   // 16

    auto issueAB = [&](int kt, int buf) {
        #pragma unroll
        for (int i = 0; i < 4; i++) {
            int idx = tid + i * 512;
            int r = idx >> 3, c8 = idx & 7;
            cp16(sA + buf * ASTG + r * 144 + c8 * 16,
                 A + (size_t)(row0 + r) * K + kt * 64 + c8 * 8);
        }
        #pragma unroll
        for (int i = 0; i < 2; i++) {
            int idx = tid + i * 512;
            int r = idx >> 3, c8 = idx & 7;
            cp16(sB + buf * BSTG + r * 144 + c8 * 16,
                 Bt + (size_t)(col0 + r) * K + kt * 64 + c8 * 8);
        }
        cp_commit();
    };

    issueAB(0, 0); issueAB(1, 1);

    for (int kt = 0; kt < NKT; kt++) {
        if (kt + 1 < NKT) cp_wait<1>();
        else              cp_wait<0>();
        __syncthreads();
        if (kt + 2 < NKT) issueAB(kt + 2, (kt + 2) % 3);

        const int buf = kt % 3;
        const uint32_t aB = aBase + buf * ASTG;
        const uint32_t bB = bBase + buf * BSTG;
        #pragma unroll
        for (int s = 0; s < 4; s++) {
            uint32_t af[4][4], bf[4][2];
            #pragma unroll
            for (int fm = 0; fm < 4; fm++)
                ldsm4(af[fm][0], af[fm][1], af[fm][2], af[fm][3],
                      aB + fm * (16 * 144) + s * 32);
            #pragma unroll
            for (int cb = 0; cb < 2; cb++)
                ldsm4(bf[2*cb][0], bf[2*cb][1], bf[2*cb+1][0], bf[2*cb+1][1],
                      bB + cb * (16 * 144) + s * 32);
            #pragma unroll
            for (int fm = 0; fm < 4; fm++)
                #pragma unroll
                for (int fn = 0; fn < 4; fn++)
                    mma16(c[fm][fn], af[fm], bf[fn][0], bf[fn][1]);
        }
    }

    #pragma unroll
    for (int fm = 0; fm < 4; fm++) {
        #pragma unroll
        for (int fn = 0; fn < 4; fn++) {
            const int m0 = row0 + wm + fm * 16 + g;
            const int m1 = m0 + 8;
            const int n  = col0 + wn + fn * 8 + 2 * tg;
            const float b0v = bias[n], b1v = bias[n + 1];
            float2 lo = make_float2(c[fm][fn].x + b0v, c[fm][fn].y + b1v);
            float2 hi = make_float2(c[fm][fn].z + b0v, c[fm][fn].w + b1v);
            if (MODE == 0) {
                const int which = n >> 10, cc = n & 1023, h = cc >> 6, d = cc & 63;
                const int b = m0 >> 11, t = m0 & 2047;   // same b for m0, m1
                if (which < 2) {
                    __half* dst = (which == 0) ? g_q : g_k;
                    *(__half2*)&dst[((size_t)((b * HH + h) * TT + t)) * DHD + d] =
                        __floats2half2_rn(lo.x, lo.y);
                    *(__half2*)&dst[((size_t)((b * HH + h) * TT + t + 8)) * DHD + d] =
                        __floats2half2_rn(hi.x, hi.y);
                } else {
                    __half* dst = g_vt + (size_t)(b * HH + h) * DHD * TT;
                    dst[(size_t)d * TT + t]           = __float2half_rn(lo.x);
                    dst[(size_t)(d + 1) * TT + t]     = __float2half_rn(lo.y);
                    dst[(size_t)d * TT + t + 8]       = __float2half_rn(hi.x);
                    dst[(size_t)(d + 1) * TT + t + 8] = __float2half_rn(hi.y);
                }
            } else {
                *(float2*)&Out[(size_t)m0 * N + n] = lo;
                *(float2*)&Out[(size_t)m1 * N + n] = hi;
            }
        }
    }
}

// ---------------------------------------------------------------------------
// f16 tensor-core causal flash attention, 128-row q tiles x 128-key tiles,
// 256 threads (8 warps x m16), 2-stage cp.async KV ring, 2 CTAs/SM.
// Register-resident P; ex2.approx.f16x2 exponent; row-sum via MMA against a
// CONSTANT ones B-fragment (lanes with lane>>2==0 hold half2(1,1)) — no smem
// ones-row, no extra LDSM. Q fragments reloaded per tile (frees 16 regs).
// K rows 144 B, V^T rows 272 B (conflict-free LDSM).
// ---------------------------------------------------------------------------
#define QB2 18432     // Q tile: 128 x 144 B
#define KTB 18432     // K tile: 128 rows x 144 B
#define VTB 17408     // V^T tile: 64 rows x 272 B
#define SCL2E 0.1803368801111204f   // (1/8) * log2(e)

__global__ __launch_bounds__(256, 2)
void attn_kernel()
{
    extern __shared__ __align__(16) char smc[];
    const uint32_t sQ = smem_u32(smc);
    const uint32_t sK = sQ + QB2;               // 2 x KTB
    const uint32_t sV = sK + 2 * KTB;           // 2 x VTB

    const int bh = blockIdx.y;
    const int qt = (int)gridDim.x - 1 - (int)blockIdx.x;  // big tiles first
    const int q0 = qt * 128;
    const int tid = threadIdx.x, lane = tid & 31, wid = tid >> 5;
    const int wm = wid * 16;
    const int g = lane >> 2, tg = lane & 3;

    const __half* Qg = g_q  + (size_t)bh * TT * DHD;
    const __half* Kg = g_k  + (size_t)bh * TT * DHD;
    const __half* Vg = g_vt + (size_t)bh * DHD * TT;

    auto issueKV = [&](int kt, int buf) {
        const int k0 = kt * 128;
        #pragma unroll
        for (int i = 0; i < 4; i++) {
            int idx = tid + i * 256;
            int r = idx >> 3, c8 = idx & 7;
            cp16(sK + buf * KTB + r * 144 + c8 * 16,
                 Kg + (size_t)(k0 + r) * DHD + c8 * 8);
        }
        #pragma unroll
        for (int i = 0; i < 4; i++) {
            int idx = tid + i * 256;
            int r = idx >> 4, c16 = idx & 15;
            cp16(sV + buf * VTB + r * 272 + c16 * 16,
                 Vg + (size_t)r * TT + k0 + c16 * 8);
        }
        cp_commit();
    };

    const int NT = qt + 1;

    // prologue: Q + KV0 (group 0), KV1 (group 1; keys [128,256) always exist)
    #pragma unroll
    for (int i = 0; i < 4; i++) {
        int idx = tid + i * 256;
        int r = idx >> 3, c8 = idx & 7;
        cp16(sQ + r * 144 + c8 * 16, Qg + (size_t)(q0 + r) * DHD + c8 * 8);
    }
    issueKV(0, 0);   // commits Q too (same group)
    issueKV(1, 1);

    // ldmatrix bases
    const uint32_t aQ = sQ + (wm + (lane & 15)) * 144 + (lane >> 4) * 16;
    const uint32_t kOffK = (((lane >> 4) << 3) + (lane & 7)) * 144
                         + ((lane >> 3) & 1) * 16;
    const uint32_t kOffV = (((lane >> 4) << 3) + (lane & 7)) * 272
                         + ((lane >> 3) & 1) * 16;

    // constant ones B-fragment for the l (row-sum) MMA: column n=0 holds 1.0
    const uint32_t econst = (g == 0) ? 0x3C003C00u : 0u;

    float4 o[8], oe;
    #pragma unroll
    for (int fn = 0; fn < 8; fn++) o[fn] = make_float4(0.f, 0.f, 0.f, 0.f);
    oe = make_float4(0.f, 0.f, 0.f, 0.f);
    float m0 = -INFINITY, m1 = -INFINITY;
    const int r0g = q0 + wm + g, r1g = r0g + 8;

    for (int kt = 0; kt < NT; kt++) {
        const int k0 = kt * 128;
        if (kt + 1 < NT) cp_wait<1>();
        else             cp_wait<0>();
        __syncthreads();

        const int buf = kt & 1;
        const uint32_t bK = sK + buf * KTB + kOffK;
        const uint32_t bV = sV + buf * VTB + kOffV;

        // S = Q K^T  (m16 x n128), raw scores; Q frags reloaded per k-chunk
        float4 s[16];
        #pragma unroll
        for (int fn = 0; fn < 16; fn++) s[fn] = make_float4(0.f, 0.f, 0.f, 0.f);
        #pragma unroll
        for (int kc = 0; kc < 4; kc++) {
            uint32_t qf[4];
            ldsm4(qf[0], qf[1], qf[2], qf[3], aQ + kc * 32);
            #pragma unroll
            for (int cb = 0; cb < 8; cb++) {
                uint32_t b0, b1, b2, b3;
                ldsm4(b0, b1, b2, b3, bK + cb * (16 * 144) + kc * 32);
                mma16(s[2*cb],   qf, b0, b1);
                mma16(s[2*cb+1], qf, b2, b3);
            }
        }

        // causal mask — q tiles and key tiles align, so only kt == qt masks
        if (kt == NT - 1) {
            #pragma unroll
            for (int fn = 0; fn < 16; fn++) {
                int c0 = k0 + fn * 8 + 2 * tg, c1 = c0 + 1;
                if (c0 > r0g) s[fn].x = -INFINITY;
                if (c1 > r0g) s[fn].y = -INFINITY;
                if (c0 > r1g) s[fn].z = -INFINITY;
                if (c1 > r1g) s[fn].w = -INFINITY;
            }
        }

        // row max (rows g, g+8)
        float rmax0 = -INFINITY, rmax1 = -INFINITY;
        #pragma unroll
        for (int fn = 0; fn < 16; fn++) {
            rmax0 = fmaxf(rmax0, fmaxf(s[fn].x, s[fn].y));
            rmax1 = fmaxf(rmax1, fmaxf(s[fn].z, s[fn].w));
        }
        rmax0 = fmaxf(rmax0, __shfl_xor_sync(0xffffffffu, rmax0, 1));
        rmax0 = fmaxf(rmax0, __shfl_xor_sync(0xffffffffu, rmax0, 2));
        rmax1 = fmaxf(rmax1, __shfl_xor_sync(0xffffffffu, rmax1, 1));
        rmax1 = fmaxf(rmax1, __shfl_xor_sync(0xffffffffu, rmax1, 2));
        const float mn0 = fmaxf(m0, rmax0), mn1 = fmaxf(m1, rmax1);
        const float al0 = ex2((m0 - mn0) * SCL2E), al1 = ex2((m1 - mn1) * SCL2E);
        m0 = mn0; m1 = mn1;
        const float mns0 = mn0 * SCL2E, mns1 = mn1 * SCL2E;

        // rescale O and the l-accumulator fragment
        #pragma unroll
        for (int fn = 0; fn < 8; fn++) {
            o[fn].x *= al0; o[fn].y *= al0;
            o[fn].z *= al1; o[fn].w *= al1;
        }
        oe.x *= al0; oe.z *= al1;

        // O += P @ V ; l += P @ ones — P packed + exponentiated per kc
        // (pf liveness = 4 regs; MUFU overlaps the V LDSM/MMA stream)
        #pragma unroll
        for (int kc = 0; kc < 8; kc++) {
            uint32_t pf[4];
            pf[0] = ex2h2(pack_f16x2(fmaf(s[2*kc].x,   SCL2E, -mns0),
                                     fmaf(s[2*kc].y,   SCL2E, -mns0)));
            pf[1] = ex2h2(pack_f16x2(fmaf(s[2*kc].z,   SCL2E, -mns1),
                                     fmaf(s[2*kc].w,   SCL2E, -mns1)));
            pf[2] = ex2h2(pack_f16x2(fmaf(s[2*kc+1].x, SCL2E, -mns0),
                                     fmaf(s[2*kc+1].y, SCL2E, -mns0)));
            pf[3] = ex2h2(pack_f16x2(fmaf(s[2*kc+1].z, SCL2E, -mns1),
                                     fmaf(s[2*kc+1].w, SCL2E, -mns1)));
            #pragma unroll
            for (int cb = 0; cb < 4; cb++) {
                uint32_t b0, b1, b2, b3;
                ldsm4(b0, b1, b2, b3, bV + cb * (16 * 272) + kc * 32);
                mma16(o[2*cb],   pf, b0, b1);
                mma16(o[2*cb+1], pf, b2, b3);
            }
            mma16(oe, pf, econst, econst);
        }

        // free this buffer for kt+2, then prefetch
        __syncthreads();
        if (kt + 2 < NT) issueKV(kt + 2, buf);
    }

    // l lives in column 64 (frag col 0) -> tg==0 lanes; broadcast in quad
    const int src = lane & ~3;
    const float l0 = __shfl_sync(0xffffffffu, oe.x, src);
    const float l1 = __shfl_sync(0xffffffffu, oe.z, src);

    // finalize -> g_ao (f16), token-major
    const int b = bh >> 4, h = bh & 15;
    const float inv0 = 1.f / l0, inv1 = 1.f / l1;
    #pragma unroll
    for (int fn = 0; fn < 8; fn++) {
        const int d = fn * 8 + 2 * tg;
        *(__half2*)&g_ao[(size_t)(b * TT + r0g) * CC + h * 64 + d] =
            __floats2half2_rn(o[fn].x * inv0, o[fn].y * inv0);
        *(__half2*)&g_ao[(size_t)(b * TT + r1g) * CC + h * 64 + d] =
            __floats2half2_rn(o[fn].z * inv1, o[fn].w * inv1);
    }
}

// ---------------------------------------------------------------------------
extern "C" void kernel_launch(void* const* d_in, const int* in_sizes, int n_in,
                              void* d_out, int out_size)
{
    const float* x      = (const float*)d_in[0];
    const float* W_qkv  = (const float*)d_in[1];
    const float* b_qkv  = (const float*)d_in[2];
    const float* W_proj = (const float*)d_in[3];
    const float* b_proj = (const float*)d_in[4];
    float* out = (float*)d_out;

    __half* xh;     cudaGetSymbolAddress((void**)&xh,     g_xh);
    __half* wqkvT;  cudaGetSymbolAddress((void**)&wqkvT,  g_wqkvT);
    __half* wprojT; cudaGetSymbolAddress((void**)&wprojT, g_wprojT);
    __half* ao;     cudaGetSymbolAddress((void**)&ao,     g_ao);

    // 0) convert x to f16; transpose+convert weights to f16
    cvt_f32_f16<<<(NTOK*CC/4 + 255)/256, 256>>>(x, xh, NTOK*CC/4);
    transpose_cvt_h<<<dim3(3*CC/32, CC/32), dim3(32, 8)>>>(W_qkv,  wqkvT,  CC, 3*CC);
    transpose_cvt_h<<<dim3(CC/32,   CC/32), dim3(32, 8)>>>(W_proj, wprojT, CC, CC);

    const int gemm_smem = 3 * (ASTG + BSTG);   // 165888
    cudaFuncSetAttribute(mma_gemm<0>, cudaFuncAttributeMaxDynamicSharedMemorySize,
                         gemm_smem);
    cudaFuncSetAttribute(mma_gemm<1>, cudaFuncAttributeMaxDynamicSharedMemorySize,
                         gemm_smem);

    // 1) QKV GEMM (f16 mma, 256x128 tiles, 512 threads) + scatter
    mma_gemm<0><<<dim3(3*CC/128, NTOK/256), 512, gemm_smem>>>(xh, wqkvT, b_qkv,
                                                              nullptr, NTOK, 3*CC, CC);

    // 2) causal flash attention (register P, const-frag row-sum, 2 CTAs/SM)
    const int attn_smem = QB2 + 2 * KTB + 2 * VTB;   // 90112
    cudaFuncSetAttribute(attn_kernel, cudaFuncAttributeMaxDynamicSharedMemorySize,
                         attn_smem);
    attn_kernel<<<dim3(TT/128, BB*HH), 256, attn_smem>>>();

    // 3) output projection (f16 mma, 256x128 tiles, 512 threads)
    mma_gemm<1><<<dim3(CC/128, NTOK/256), 512, gemm_smem>>>(ao, wprojT, b_proj,
                                                            out, NTOK, CC, CC);
}